// round 2
// baseline (speedup 1.0000x reference)
#include <cuda_runtime.h>
#include <math.h>

#define VOCAB 32000
#define HDIM  512
#define BATCH 128
#define ENCL  64
#define NSTEP 31
#define MROWS (BATCH * ENCL)   // 8192

// ---------------- scratch (static device globals; no allocation) ----------------
__device__ float g_P[MROWS * HDIM];        // enc @ W1a^T  (time-invariant)
__device__ float g_a2[MROWS * HDIM];
__device__ float g_a3[MROWS * HDIM];
__device__ float g_hid[2][BATCH * HDIM];   // ping-pong hidden state
__device__ float g_q[BATCH * HDIM];        // hid @ W1b^T + b1
__device__ float g_ctx[BATCH * HDIM];
__device__ float g_gi[BATCH * 3 * HDIM];
__device__ float g_gh[BATCH * 3 * HDIM];

// ---------------- helpers ----------------
__device__ __forceinline__ unsigned f2tf(float f) {
    unsigned u;
    asm("cvt.rna.tf32.f32 %0, %1;" : "=r"(u) : "f"(f));
    return u;
}
__device__ __forceinline__ float tanh_fast(float x) {
    float y;
    asm("tanh.approx.f32 %0, %1;" : "=f"(y) : "f"(x));
    return y;
}
__device__ __forceinline__ void mma_tf32(float c[4], const unsigned a[4], const unsigned b[2]) {
    asm volatile(
        "mma.sync.aligned.m16n8k8.row.col.f32.tf32.tf32.f32 "
        "{%0,%1,%2,%3}, {%4,%5,%6,%7}, {%8,%9}, {%0,%1,%2,%3};\n"
        : "+f"(c[0]), "+f"(c[1]), "+f"(c[2]), "+f"(c[3])
        : "r"(a[0]), "r"(a[1]), "r"(a[2]), "r"(a[3]), "r"(b[0]), "r"(b[1]));
}

// ---------------- generic GEMM:  C[M,N] = act(A[M,K] * W[N,K]^T + bias) ----------------
// AMODE 0: A read directly (row stride lda)
// AMODE 1: A element = tanh(P[row,k] + Q[row>>6, k])   (attention layer-1 fusion)
// AMODE 2: A element = k<HDIM ? EMB[TGT[row*32], k] : Q[row, k-HDIM]   (GRU input concat)
// ACT   1: epilogue tanh
template <int AMODE, int ACT>
__global__ __launch_bounds__(256) void gemm_kernel(
    const float* __restrict__ A, int lda,
    const float* __restrict__ W, int ldw,
    const float* __restrict__ bias,
    float* __restrict__ C, size_t ldc,
    int M, int N, int K,
    const float* __restrict__ Q,
    const float* __restrict__ EMB,
    const int* __restrict__ TGT)
{
    __shared__ unsigned As[2][16][136];   // [k][m], pad 8 -> conflict-free frag loads
    __shared__ unsigned Ws[2][16][136];   // [k][n]

    const int tid    = threadIdx.x;
    const int warpid = tid >> 5, lane = tid & 31;
    const int wm = warpid >> 1, wn = warpid & 1;     // 4 x 2 warp grid
    const int gid = lane >> 2, tidg = lane & 3;
    const int bm0 = blockIdx.y * 128, bn0 = blockIdx.x * 128;
    const int lr = tid >> 2;           // 0..63
    const int kq = (tid & 3) * 4;      // 0,4,8,12

    float acc[2][8][4];
    #pragma unroll
    for (int mi = 0; mi < 2; mi++)
        #pragma unroll
        for (int ni = 0; ni < 8; ni++)
            #pragma unroll
            for (int qq = 0; qq < 4; qq++) acc[mi][ni][qq] = 0.f;

    const int nk = K >> 4;
    float4 pa[2], pw[2];

    auto fetch = [&](int kt) {
        const int k0 = kt << 4;
        #pragma unroll
        for (int it = 0; it < 2; it++) {
            const int r = lr + it * 64;
            const int arow = bm0 + r;
            float4 v = make_float4(0.f, 0.f, 0.f, 0.f);
            if (arow < M) {
                if (AMODE == 0) {
                    v = *(const float4*)(A + (size_t)arow * lda + k0 + kq);
                } else if (AMODE == 1) {
                    float4 p = *(const float4*)(A + (size_t)arow * lda + k0 + kq);
                    const float* qr = Q + ((arow >> 6) << 9) + k0 + kq;
                    v.x = tanh_fast(p.x + qr[0]);
                    v.y = tanh_fast(p.y + qr[1]);
                    v.z = tanh_fast(p.z + qr[2]);
                    v.w = tanh_fast(p.w + qr[3]);
                } else {
                    const int kk = k0 + kq;
                    if (kk < HDIM) {
                        int tg = TGT[arow * 32];
                        tg = max(0, min(tg, VOCAB - 1));   // safety clamp
                        v = *(const float4*)(EMB + (size_t)tg * HDIM + kk);
                    } else {
                        v = *(const float4*)(Q + ((size_t)arow << 9) + (kk - HDIM));
                    }
                }
            }
            pa[it] = v;
            const int wrow = bn0 + r;
            float4 wv = make_float4(0.f, 0.f, 0.f, 0.f);
            if (wrow < N) wv = *(const float4*)(W + (size_t)wrow * ldw + k0 + kq);
            pw[it] = wv;
        }
    };
    auto store_smem = [&](int buf) {
        #pragma unroll
        for (int it = 0; it < 2; it++) {
            const int r = lr + it * 64;
            As[buf][kq + 0][r] = f2tf(pa[it].x);
            As[buf][kq + 1][r] = f2tf(pa[it].y);
            As[buf][kq + 2][r] = f2tf(pa[it].z);
            As[buf][kq + 3][r] = f2tf(pa[it].w);
            Ws[buf][kq + 0][r] = f2tf(pw[it].x);
            Ws[buf][kq + 1][r] = f2tf(pw[it].y);
            Ws[buf][kq + 2][r] = f2tf(pw[it].z);
            Ws[buf][kq + 3][r] = f2tf(pw[it].w);
        }
    };

    fetch(0);
    store_smem(0);
    __syncthreads();

    for (int kt = 0; kt < nk; kt++) {
        const int buf = kt & 1;
        if (kt + 1 < nk) fetch(kt + 1);   // overlap global latency with compute

        #pragma unroll
        for (int ks = 0; ks < 2; ks++) {
            const int kb = ks * 8;
            unsigned af[2][4], bf[8][2];
            #pragma unroll
            for (int mi = 0; mi < 2; mi++) {
                const int m0 = wm * 32 + mi * 16 + gid;
                af[mi][0] = As[buf][kb + tidg][m0];
                af[mi][1] = As[buf][kb + tidg][m0 + 8];
                af[mi][2] = As[buf][kb + tidg + 4][m0];
                af[mi][3] = As[buf][kb + tidg + 4][m0 + 8];
            }
            #pragma unroll
            for (int ni = 0; ni < 8; ni++) {
                const int n0 = wn * 64 + ni * 8 + gid;
                bf[ni][0] = Ws[buf][kb + tidg][n0];
                bf[ni][1] = Ws[buf][kb + tidg + 4][n0];
            }
            #pragma unroll
            for (int mi = 0; mi < 2; mi++)
                #pragma unroll
                for (int ni = 0; ni < 8; ni++)
                    mma_tf32(acc[mi][ni], af[mi], bf[ni]);
        }

        if (kt + 1 < nk) store_smem((kt + 1) & 1);
        __syncthreads();
    }

    // epilogue: bias (+ optional tanh)
    #pragma unroll
    for (int mi = 0; mi < 2; mi++) {
        #pragma unroll
        for (int ni = 0; ni < 8; ni++) {
            const int col = bn0 + wn * 64 + ni * 8 + tidg * 2;
            const float b0v = bias ? bias[col] : 0.f;
            const float b1v = bias ? bias[col + 1] : 0.f;
            const int row0 = bm0 + wm * 32 + mi * 16 + gid;
            if (row0 < M) {
                float v0 = acc[mi][ni][0] + b0v, v1 = acc[mi][ni][1] + b1v;
                if (ACT) { v0 = tanh_fast(v0); v1 = tanh_fast(v1); }
                C[(size_t)row0 * ldc + col]     = v0;
                C[(size_t)row0 * ldc + col + 1] = v1;
            }
            const int row1 = row0 + 8;
            if (row1 < M) {
                float v2 = acc[mi][ni][2] + b0v, v3 = acc[mi][ni][3] + b1v;
                if (ACT) { v2 = tanh_fast(v2); v3 = tanh_fast(v3); }
                C[(size_t)row1 * ldc + col]     = v2;
                C[(size_t)row1 * ldc + col + 1] = v3;
            }
        }
    }
}

// ---------------- init hidden state ----------------
__global__ void copy_hid_kernel(const float* __restrict__ src) {
    const int i = blockIdx.x * blockDim.x + threadIdx.x;
    if (i < BATCH * HDIM) g_hid[0][i] = src[i];
}

// ---------------- e = a3 . v ; softmax over L ; ctx = alpha^T enc ----------------
__global__ __launch_bounds__(256) void softmax_ctx_kernel(
    const float* __restrict__ a3, const float* __restrict__ v,
    const float* __restrict__ enc, float* __restrict__ ctx)
{
    __shared__ float e[ENCL];
    __shared__ float alpha[ENCL];
    const int b = blockIdx.x;
    const int tid = threadIdx.x;
    const int warp = tid >> 5, lane = tid & 31;

    #pragma unroll
    for (int li = 0; li < 8; li++) {
        const int l = warp * 8 + li;
        const float* row = a3 + ((size_t)b * ENCL + l) * HDIM;
        float s = 0.f;
        for (int j = lane; j < HDIM; j += 32) s += row[j] * v[j];
        #pragma unroll
        for (int o = 16; o; o >>= 1) s += __shfl_xor_sync(0xffffffffu, s, o);
        if (lane == 0) e[l] = s;
    }
    __syncthreads();
    if (warp == 0) {
        const float e0 = e[lane], e1 = e[lane + 32];
        float m = fmaxf(e0, e1);
        #pragma unroll
        for (int o = 16; o; o >>= 1) m = fmaxf(m, __shfl_xor_sync(0xffffffffu, m, o));
        const float x0 = expf(e0 - m), x1 = expf(e1 - m);
        float s = x0 + x1;
        #pragma unroll
        for (int o = 16; o; o >>= 1) s += __shfl_xor_sync(0xffffffffu, s, o);
        const float inv = 1.f / s;
        alpha[lane]      = x0 * inv;
        alpha[lane + 32] = x1 * inv;
    }
    __syncthreads();
    for (int j = tid; j < HDIM; j += 256) {
        float s = 0.f;
        #pragma unroll
        for (int l = 0; l < ENCL; l++)
            s += alpha[l] * enc[((size_t)b * ENCL + l) * HDIM + j];
        ctx[b * HDIM + j] = s;
    }
}

// ---------------- GRU gate combine ----------------
__global__ void gru_kernel(const float* __restrict__ gi, const float* __restrict__ gh,
                           const float* __restrict__ h, float* __restrict__ hn)
{
    const int b = blockIdx.x, j = threadIdx.x;
    const int o = b * 3 * HDIM;
    const float r = 1.f / (1.f + expf(-(gi[o + j] + gh[o + j])));
    const float z = 1.f / (1.f + expf(-(gi[o + HDIM + j] + gh[o + HDIM + j])));
    const float n = tanhf(gi[o + 2 * HDIM + j] + r * gh[o + 2 * HDIM + j]);
    const float hv = h[b * HDIM + j];
    hn[b * HDIM + j] = (1.f - z) * n + z * hv;
}

// ---------------- in-place log-softmax over one row of 32000 (single pass, regs) ----------------
__global__ __launch_bounds__(1024) void logsoftmax_kernel(float* __restrict__ out, int t) {
    const int b = blockIdx.x;
    float* row = out + ((size_t)b * NSTEP + t) * VOCAB;
    const int tid = threadIdx.x;
    __shared__ float sm[32];

    float r[32];
    float m = -1e30f;
    #pragma unroll
    for (int i = 0; i < 32; i++) {
        const int idx = tid + (i << 10);
        r[i] = (idx < VOCAB) ? row[idx] : -1e30f;
        m = fmaxf(m, r[i]);
    }
    #pragma unroll
    for (int o = 16; o; o >>= 1) m = fmaxf(m, __shfl_xor_sync(0xffffffffu, m, o));
    if ((tid & 31) == 0) sm[tid >> 5] = m;
    __syncthreads();
    if (tid == 0) {
        float v = sm[0];
        for (int i = 1; i < 32; i++) v = fmaxf(v, sm[i]);
        sm[0] = v;
    }
    __syncthreads();
    m = sm[0];

    float s = 0.f;
    #pragma unroll
    for (int i = 0; i < 32; i++) {
        const int idx = tid + (i << 10);
        if (idx < VOCAB) s += expf(r[i] - m);
    }
    #pragma unroll
    for (int o = 16; o; o >>= 1) s += __shfl_xor_sync(0xffffffffu, s, o);
    __syncthreads();   // all reads of sm[0] done before overwrite
    if ((tid & 31) == 0) sm[tid >> 5] = s;
    __syncthreads();
    if (tid == 0) {
        float v = 0.f;
        for (int i = 0; i < 32; i++) v += sm[i];
        sm[0] = v;
    }
    __syncthreads();
    const float lse = m + logf(sm[0]);

    #pragma unroll
    for (int i = 0; i < 32; i++) {
        const int idx = tid + (i << 10);
        if (idx < VOCAB) row[idx] = r[i] - lse;
    }
}

// ---------------- launch ----------------
extern "C" void kernel_launch(void* const* d_in, const int* in_sizes, int n_in,
                              void* d_out, int out_size)
{
    const float* enc       = (const float*)d_in[0];
    const float* ench      = (const float*)d_in[1];
    const int* tgt         = (const int*)d_in[2];    // int32 (JAX x64 disabled)
    const float* emb       = (const float*)d_in[3];
    const float* W1        = (const float*)d_in[4];
    const float* b1        = (const float*)d_in[5];
    const float* W2        = (const float*)d_in[6];
    const float* b2        = (const float*)d_in[7];
    const float* W3        = (const float*)d_in[8];
    const float* b3        = (const float*)d_in[9];
    const float* av        = (const float*)d_in[10];
    const float* Wih       = (const float*)d_in[11];
    const float* Whh       = (const float*)d_in[12];
    const float* bih       = (const float*)d_in[13];
    const float* bhh       = (const float*)d_in[14];
    const float* oW        = (const float*)d_in[15];
    const float* ob        = (const float*)d_in[16];
    float* out = (float*)d_out;

    float *P, *a2, *a3, *hidb, *q, *ctx, *gi, *gh;
    cudaGetSymbolAddress((void**)&P,    g_P);
    cudaGetSymbolAddress((void**)&a2,   g_a2);
    cudaGetSymbolAddress((void**)&a3,   g_a3);
    cudaGetSymbolAddress((void**)&hidb, g_hid);
    cudaGetSymbolAddress((void**)&q,    g_q);
    cudaGetSymbolAddress((void**)&ctx,  g_ctx);
    cudaGetSymbolAddress((void**)&gi,   g_gi);
    cudaGetSymbolAddress((void**)&gh,   g_gh);

    copy_hid_kernel<<<(BATCH * HDIM + 255) / 256, 256>>>(ench);

    // P = enc @ W1[:, :H]^T   (time-invariant; no bias)
    gemm_kernel<0, 0><<<dim3(HDIM / 128, MROWS / 128), 256>>>(
        enc, HDIM, W1, 2 * HDIM, nullptr, P, HDIM, MROWS, HDIM, HDIM,
        nullptr, nullptr, nullptr);

    for (int t = 0; t < NSTEP; t++) {
        float* hi = hidb + (t & 1) * (BATCH * HDIM);
        float* ho = hidb + ((t + 1) & 1) * (BATCH * HDIM);

        // q = hid @ W1[:, H:]^T + b1
        gemm_kernel<0, 0><<<dim3(HDIM / 128, 1), 256>>>(
            hi, HDIM, W1 + HDIM, 2 * HDIM, b1, q, HDIM, BATCH, HDIM, HDIM,
            nullptr, nullptr, nullptr);

        // a2 = tanh( tanh(P+q) @ W2^T + b2 )    (layer-1 tanh fused into A-load)
        gemm_kernel<1, 1><<<dim3(HDIM / 128, MROWS / 128), 256>>>(
            P, HDIM, W2, HDIM, b2, a2, HDIM, MROWS, HDIM, HDIM,
            q, nullptr, nullptr);

        // a3 = tanh( a2 @ W3^T + b3 )
        gemm_kernel<0, 1><<<dim3(HDIM / 128, MROWS / 128), 256>>>(
            a2, HDIM, W3, HDIM, b3, a3, HDIM, MROWS, HDIM, HDIM,
            nullptr, nullptr, nullptr);

        softmax_ctx_kernel<<<BATCH, 256>>>(a3, av, enc, ctx);

        // gh = hid @ Whh^T + bhh
        gemm_kernel<0, 0><<<dim3(3 * HDIM / 128, 1), 256>>>(
            hi, HDIM, Whh, HDIM, bhh, gh, 3 * HDIM, BATCH, 3 * HDIM, HDIM,
            nullptr, nullptr, nullptr);

        // gi = [embed[tgt_t], ctx] @ Wih^T + bih   (gather+concat fused into A-load)
        gemm_kernel<2, 0><<<dim3(3 * HDIM / 128, 1), 256>>>(
            nullptr, 0, Wih, 2 * HDIM, bih, gi, 3 * HDIM, BATCH, 3 * HDIM, 2 * HDIM,
            ctx, emb, tgt + t);

        gru_kernel<<<BATCH, HDIM>>>(gi, gh, hi, ho);

        // logits -> d_out (strided rows), then in-place log-softmax
        gemm_kernel<0, 0><<<dim3(VOCAB / 128, 1), 256>>>(
            ho, HDIM, oW, HDIM, ob, out + (size_t)t * VOCAB, (size_t)NSTEP * VOCAB,
            BATCH, VOCAB, HDIM, nullptr, nullptr, nullptr);

        logsoftmax_kernel<<<BATCH, 1024>>>(out, t);
    }
}

// round 3
// speedup vs baseline: 1.6940x; 1.6940x over previous
#include <cuda_runtime.h>
#include <cuda_bf16.h>
#include <math.h>

#define VOCAB 32000
#define HDIM  512
#define BATCH 128
#define ENCL  64
#define NSTEP 31
#define MROWS (BATCH * ENCL)   // 8192

// ---------------- scratch (static device globals; no allocation) ----------------
__device__ float g_P[MROWS * HDIM];        // enc @ W1a^T  (time-invariant)
__device__ float g_a2[MROWS * HDIM];
__device__ float g_a3[MROWS * HDIM];
__device__ float g_hid[2][BATCH * HDIM];   // ping-pong hidden state
__device__ float g_qgh[BATCH * 2048];      // [q(512) | gh(1536)] per batch row
__device__ float g_ctx[BATCH * HDIM];
__device__ float g_gi[BATCH * 3 * HDIM];
__device__ float g_bqh[2048];              // [b1 | bhh]

// bf16 weight copies (converted once per replay)
__device__ __nv_bfloat16 g_Wp  [HDIM * HDIM];          // W1[:, :H]
__device__ __nv_bfloat16 g_Wqh [2048 * HDIM];          // [W1[:, H:] ; Whh]
__device__ __nv_bfloat16 g_W2  [HDIM * HDIM];
__device__ __nv_bfloat16 g_W3  [HDIM * HDIM];
__device__ __nv_bfloat16 g_Wih [3 * HDIM * 2 * HDIM];
__device__ __nv_bfloat16 g_Wo  [VOCAB * HDIM];

// ---------------- helpers ----------------
__device__ __forceinline__ unsigned bf2(float lo, float hi) {
    unsigned u;
    asm("cvt.rn.bf16x2.f32 %0, %1, %2;" : "=r"(u) : "f"(hi), "f"(lo));
    return u;
}
__device__ __forceinline__ float tanh_fast(float x) {
    float y;
    asm("tanh.approx.f32 %0, %1;" : "=f"(y) : "f"(x));
    return y;
}
__device__ __forceinline__ void mma_bf16(float c[4], const unsigned a[4], const unsigned b[2]) {
    asm volatile(
        "mma.sync.aligned.m16n8k16.row.col.f32.bf16.bf16.f32 "
        "{%0,%1,%2,%3}, {%4,%5,%6,%7}, {%8,%9}, {%0,%1,%2,%3};\n"
        : "+f"(c[0]), "+f"(c[1]), "+f"(c[2]), "+f"(c[3])
        : "r"(a[0]), "r"(a[1]), "r"(a[2]), "r"(a[3]), "r"(b[0]), "r"(b[1]));
}

// ---------------- weight conversion (fp32 -> bf16, strided source) ----------------
__global__ void conv_kernel(__nv_bfloat16* __restrict__ dst, const float* __restrict__ src,
                            int rows, int cols, int sld, int soff) {
    const int idx = blockIdx.x * blockDim.x + threadIdx.x;
    if (idx >= rows * cols) return;
    const int r = idx / cols, c = idx - r * cols;
    dst[idx] = __float2bfloat16(src[(size_t)r * sld + soff + c]);
}

__global__ void init_misc_kernel(const float* __restrict__ ench,
                                 const float* __restrict__ b1,
                                 const float* __restrict__ bhh) {
    const int i = blockIdx.x * blockDim.x + threadIdx.x;
    if (i < BATCH * HDIM) g_hid[0][i] = ench[i];
    if (i < 2048) g_bqh[i] = (i < HDIM) ? b1[i] : bhh[i - HDIM];
}

// ---------------- GEMM:  C[M,N] = act(A[M,K] * W[N,K]^T + bias),  W in bf16 ----------------
// Tiles: CTA 128x128, warp 32x64 (4x2 warps), K-tile 16. bf16 m16n8k16 MMA, fp32 accum.
// AMODE 0: A read directly (fp32, row stride lda)
// AMODE 1: A element = tanh(P[row,k] + Q[row>>6, k])   (attention layer-1 fusion)
// AMODE 2: A element = k<HDIM ? EMB[TGT[row*32], k] : Q[row, k-HDIM]   (GRU input concat)
// ACT   1: epilogue tanh
// All launches have M,N multiples of tile -> no bounds checks.
template <int AMODE, int ACT>
__global__ __launch_bounds__(256) void gemm_kernel(
    const float* __restrict__ A, int lda,
    const __nv_bfloat16* __restrict__ W, int ldw,
    const float* __restrict__ bias,
    float* __restrict__ C, size_t ldc,
    int M, int N, int K,
    const float* __restrict__ Q, int qld,
    const float* __restrict__ EMB,
    const int* __restrict__ TGT)
{
    __shared__ unsigned As[2][8][136];   // [k-pair][m], bf16x2, pad -> conflict-free frags
    __shared__ unsigned Ws[2][8][136];   // [k-pair][n]

    const int tid    = threadIdx.x;
    const int warpid = tid >> 5, lane = tid & 31;
    const int wm = warpid >> 1, wn = warpid & 1;     // 4 x 2 warp grid
    const int gid = lane >> 2, tidg = lane & 3;
    const int bm0 = blockIdx.y * 128, bn0 = blockIdx.x * 128;
    const int lr = tid >> 2;           // 0..63  (A loads)
    const int kq = (tid & 3) * 4;      // 0,4,8,12
    const int wr = tid >> 1;           // 0..127 (W loads)
    const int whalf = tid & 1;

    float acc[2][8][4];
    #pragma unroll
    for (int mi = 0; mi < 2; mi++)
        #pragma unroll
        for (int ni = 0; ni < 8; ni++)
            #pragma unroll
            for (int qq = 0; qq < 4; qq++) acc[mi][ni][qq] = 0.f;

    const int nk = K >> 4;
    float4 pa[2];
    uint4  pw;

    auto fetch = [&](int kt) {
        const int k0 = kt << 4;
        #pragma unroll
        for (int it = 0; it < 2; it++) {
            const int arow = bm0 + lr + it * 64;
            float4 v;
            if (AMODE == 0) {
                v = *(const float4*)(A + (size_t)arow * lda + k0 + kq);
            } else if (AMODE == 1) {
                float4 p = *(const float4*)(A + (size_t)arow * lda + k0 + kq);
                const float* qr = Q + (size_t)(arow >> 6) * qld + k0 + kq;
                v.x = tanh_fast(p.x + qr[0]);
                v.y = tanh_fast(p.y + qr[1]);
                v.z = tanh_fast(p.z + qr[2]);
                v.w = tanh_fast(p.w + qr[3]);
            } else {
                const int kk = k0 + kq;
                if (kk < HDIM) {
                    int tg = TGT[arow * 32];
                    tg = max(0, min(tg, VOCAB - 1));
                    v = *(const float4*)(EMB + (size_t)tg * HDIM + kk);
                } else {
                    v = *(const float4*)(Q + (size_t)arow * qld + (kk - HDIM));
                }
            }
            pa[it] = v;
        }
        pw = ((const uint4*)(W + (size_t)(bn0 + wr) * ldw + k0))[whalf];
    };
    auto store_smem = [&](int buf) {
        #pragma unroll
        for (int it = 0; it < 2; it++) {
            const int r = lr + it * 64;
            As[buf][(kq >> 1) + 0][r] = bf2(pa[it].x, pa[it].y);
            As[buf][(kq >> 1) + 1][r] = bf2(pa[it].z, pa[it].w);
        }
        const int kp = whalf * 4;
        Ws[buf][kp + 0][wr] = pw.x;
        Ws[buf][kp + 1][wr] = pw.y;
        Ws[buf][kp + 2][wr] = pw.z;
        Ws[buf][kp + 3][wr] = pw.w;
    };

    fetch(0);
    store_smem(0);
    __syncthreads();

    for (int kt = 0; kt < nk; kt++) {
        const int buf = kt & 1;
        if (kt + 1 < nk) fetch(kt + 1);   // overlap global latency with MMA

        unsigned af[2][4], bfr[8][2];
        #pragma unroll
        for (int mi = 0; mi < 2; mi++) {
            const int m0 = wm * 32 + mi * 16 + gid;
            af[mi][0] = As[buf][tidg][m0];
            af[mi][1] = As[buf][tidg][m0 + 8];
            af[mi][2] = As[buf][tidg + 4][m0];
            af[mi][3] = As[buf][tidg + 4][m0 + 8];
        }
        #pragma unroll
        for (int ni = 0; ni < 8; ni++) {
            const int n0 = wn * 64 + ni * 8 + gid;
            bfr[ni][0] = Ws[buf][tidg][n0];
            bfr[ni][1] = Ws[buf][tidg + 4][n0];
        }
        #pragma unroll
        for (int mi = 0; mi < 2; mi++)
            #pragma unroll
            for (int ni = 0; ni < 8; ni++)
                mma_bf16(acc[mi][ni], af[mi], bfr[ni]);

        if (kt + 1 < nk) store_smem((kt + 1) & 1);
        __syncthreads();
    }

    // epilogue: bias (+ optional tanh)
    #pragma unroll
    for (int mi = 0; mi < 2; mi++) {
        #pragma unroll
        for (int ni = 0; ni < 8; ni++) {
            const int col = bn0 + wn * 64 + ni * 8 + tidg * 2;
            const float b0v = bias ? bias[col] : 0.f;
            const float b1v = bias ? bias[col + 1] : 0.f;
            const int row0 = bm0 + wm * 32 + mi * 16 + gid;
            float v0 = acc[mi][ni][0] + b0v, v1 = acc[mi][ni][1] + b1v;
            float v2 = acc[mi][ni][2] + b0v, v3 = acc[mi][ni][3] + b1v;
            if (ACT) {
                v0 = tanh_fast(v0); v1 = tanh_fast(v1);
                v2 = tanh_fast(v2); v3 = tanh_fast(v3);
            }
            C[(size_t)row0 * ldc + col]           = v0;
            C[(size_t)row0 * ldc + col + 1]       = v1;
            C[(size_t)(row0 + 8) * ldc + col]     = v2;
            C[(size_t)(row0 + 8) * ldc + col + 1] = v3;
        }
    }
}

// ---------------- e = a3 . v ; softmax over L ; ctx = alpha^T enc ----------------
__global__ __launch_bounds__(256) void softmax_ctx_kernel(
    const float* __restrict__ a3, const float* __restrict__ v,
    const float* __restrict__ enc, float* __restrict__ ctx)
{
    __shared__ float e[ENCL];
    __shared__ float alpha[ENCL];
    const int b = blockIdx.x;
    const int tid = threadIdx.x;
    const int warp = tid >> 5, lane = tid & 31;

    #pragma unroll
    for (int li = 0; li < 8; li++) {
        const int l = warp * 8 + li;
        const float* row = a3 + ((size_t)b * ENCL + l) * HDIM;
        float s = 0.f;
        for (int j = lane; j < HDIM; j += 32) s += row[j] * v[j];
        #pragma unroll
        for (int o = 16; o; o >>= 1) s += __shfl_xor_sync(0xffffffffu, s, o);
        if (lane == 0) e[l] = s;
    }
    __syncthreads();
    if (warp == 0) {
        const float e0 = e[lane], e1 = e[lane + 32];
        float m = fmaxf(e0, e1);
        #pragma unroll
        for (int o = 16; o; o >>= 1) m = fmaxf(m, __shfl_xor_sync(0xffffffffu, m, o));
        const float x0 = expf(e0 - m), x1 = expf(e1 - m);
        float s = x0 + x1;
        #pragma unroll
        for (int o = 16; o; o >>= 1) s += __shfl_xor_sync(0xffffffffu, s, o);
        const float inv = 1.f / s;
        alpha[lane]      = x0 * inv;
        alpha[lane + 32] = x1 * inv;
    }
    __syncthreads();
    for (int j = tid; j < HDIM; j += 256) {
        float s = 0.f;
        #pragma unroll
        for (int l = 0; l < ENCL; l++)
            s += alpha[l] * enc[((size_t)b * ENCL + l) * HDIM + j];
        ctx[b * HDIM + j] = s;
    }
}

// ---------------- GRU gate combine (gh lives in qgh[:, 512:]) ----------------
__global__ void gru_kernel(const float* __restrict__ gi, const float* __restrict__ qgh,
                           const float* __restrict__ h, float* __restrict__ hn)
{
    const int b = blockIdx.x, j = threadIdx.x;
    const int o  = b * 3 * HDIM;
    const int og = b * 2048 + HDIM;
    const float r = 1.f / (1.f + expf(-(gi[o + j] + qgh[og + j])));
    const float z = 1.f / (1.f + expf(-(gi[o + HDIM + j] + qgh[og + HDIM + j])));
    const float n = tanhf(gi[o + 2 * HDIM + j] + r * qgh[og + 2 * HDIM + j]);
    const float hv = h[b * HDIM + j];
    hn[b * HDIM + j] = (1.f - z) * n + z * hv;
}

// ---------------- in-place log-softmax over one row of 32000 (single pass, regs) ----------------
__global__ __launch_bounds__(1024) void logsoftmax_kernel(float* __restrict__ out, int t) {
    const int b = blockIdx.x;
    float* row = out + ((size_t)b * NSTEP + t) * VOCAB;
    const int tid = threadIdx.x;
    __shared__ float sm[32];

    float r[32];
    float m = -1e30f;
    #pragma unroll
    for (int i = 0; i < 32; i++) {
        const int idx = tid + (i << 10);
        r[i] = (idx < VOCAB) ? row[idx] : -1e30f;
        m = fmaxf(m, r[i]);
    }
    #pragma unroll
    for (int o = 16; o; o >>= 1) m = fmaxf(m, __shfl_xor_sync(0xffffffffu, m, o));
    if ((tid & 31) == 0) sm[tid >> 5] = m;
    __syncthreads();
    if (tid == 0) {
        float v = sm[0];
        for (int i = 1; i < 32; i++) v = fmaxf(v, sm[i]);
        sm[0] = v;
    }
    __syncthreads();
    m = sm[0];

    float s = 0.f;
    #pragma unroll
    for (int i = 0; i < 32; i++) {
        const int idx = tid + (i << 10);
        if (idx < VOCAB) s += expf(r[i] - m);
    }
    #pragma unroll
    for (int o = 16; o; o >>= 1) s += __shfl_xor_sync(0xffffffffu, s, o);
    __syncthreads();
    if ((tid & 31) == 0) sm[tid >> 5] = s;
    __syncthreads();
    if (tid == 0) {
        float v = 0.f;
        for (int i = 0; i < 32; i++) v += sm[i];
        sm[0] = v;
    }
    __syncthreads();
    const float lse = m + logf(sm[0]);

    #pragma unroll
    for (int i = 0; i < 32; i++) {
        const int idx = tid + (i << 10);
        if (idx < VOCAB) row[idx] = r[i] - lse;
    }
}

// ---------------- launch ----------------
extern "C" void kernel_launch(void* const* d_in, const int* in_sizes, int n_in,
                              void* d_out, int out_size)
{
    const float* enc       = (const float*)d_in[0];
    const float* ench      = (const float*)d_in[1];
    const int* tgt         = (const int*)d_in[2];    // int32 (JAX x64 disabled)
    const float* emb       = (const float*)d_in[3];
    const float* W1        = (const float*)d_in[4];
    const float* b1        = (const float*)d_in[5];
    const float* W2        = (const float*)d_in[6];
    const float* b2        = (const float*)d_in[7];
    const float* W3        = (const float*)d_in[8];
    const float* b3        = (const float*)d_in[9];
    const float* av        = (const float*)d_in[10];
    const float* Wih       = (const float*)d_in[11];
    const float* Whh       = (const float*)d_in[12];
    const float* bih       = (const float*)d_in[13];
    const float* bhh       = (const float*)d_in[14];
    const float* oW        = (const float*)d_in[15];
    const float* ob        = (const float*)d_in[16];
    float* out = (float*)d_out;

    float *P, *a2, *a3, *hidb, *qgh, *ctx, *gi, *bqh;
    __nv_bfloat16 *Wp, *Wqh, *W2b, *W3b, *Wihb, *Wob;
    cudaGetSymbolAddress((void**)&P,    g_P);
    cudaGetSymbolAddress((void**)&a2,   g_a2);
    cudaGetSymbolAddress((void**)&a3,   g_a3);
    cudaGetSymbolAddress((void**)&hidb, g_hid);
    cudaGetSymbolAddress((void**)&qgh,  g_qgh);
    cudaGetSymbolAddress((void**)&ctx,  g_ctx);
    cudaGetSymbolAddress((void**)&gi,   g_gi);
    cudaGetSymbolAddress((void**)&bqh,  g_bqh);
    cudaGetSymbolAddress((void**)&Wp,   g_Wp);
    cudaGetSymbolAddress((void**)&Wqh,  g_Wqh);
    cudaGetSymbolAddress((void**)&W2b,  g_W2);
    cudaGetSymbolAddress((void**)&W3b,  g_W3);
    cudaGetSymbolAddress((void**)&Wihb, g_Wih);
    cudaGetSymbolAddress((void**)&Wob,  g_Wo);

    // init hidden state + concat biases
    init_misc_kernel<<<(BATCH * HDIM + 255) / 256, 256>>>(ench, b1, bhh);

    // weight conversions (fp32 -> bf16)
    conv_kernel<<<(HDIM * HDIM + 255) / 256, 256>>>(Wp,  W1, HDIM, HDIM, 2 * HDIM, 0);
    conv_kernel<<<(HDIM * HDIM + 255) / 256, 256>>>(Wqh, W1, HDIM, HDIM, 2 * HDIM, HDIM);
    conv_kernel<<<(3 * HDIM * HDIM + 255) / 256, 256>>>(Wqh + HDIM * HDIM, Whh, 3 * HDIM, HDIM, HDIM, 0);
    conv_kernel<<<(HDIM * HDIM + 255) / 256, 256>>>(W2b, W2, HDIM, HDIM, HDIM, 0);
    conv_kernel<<<(HDIM * HDIM + 255) / 256, 256>>>(W3b, W3, HDIM, HDIM, HDIM, 0);
    conv_kernel<<<(3 * HDIM * 2 * HDIM + 255) / 256, 256>>>(Wihb, Wih, 3 * HDIM, 2 * HDIM, 2 * HDIM, 0);
    conv_kernel<<<(VOCAB * HDIM + 255) / 256, 256>>>(Wob, oW, VOCAB, HDIM, HDIM, 0);

    // P = enc @ W1[:, :H]^T   (time-invariant; no bias)
    gemm_kernel<0, 0><<<dim3(HDIM / 128, MROWS / 128), 256>>>(
        enc, HDIM, Wp, HDIM, nullptr, P, HDIM, MROWS, HDIM, HDIM,
        nullptr, 0, nullptr, nullptr);

    for (int t = 0; t < NSTEP; t++) {
        float* hi = hidb + (t & 1) * (BATCH * HDIM);
        float* ho = hidb + ((t + 1) & 1) * (BATCH * HDIM);

        // [q | gh] = hid @ [W1b ; Whh]^T + [b1 | bhh]
        gemm_kernel<0, 0><<<dim3(2048 / 128, 1), 256>>>(
            hi, HDIM, Wqh, HDIM, bqh, qgh, 2048, BATCH, 2048, HDIM,
            nullptr, 0, nullptr, nullptr);

        // a2 = tanh( tanh(P+q) @ W2^T + b2 )
        gemm_kernel<1, 1><<<dim3(HDIM / 128, MROWS / 128), 256>>>(
            P, HDIM, W2b, HDIM, b2, a2, HDIM, MROWS, HDIM, HDIM,
            qgh, 2048, nullptr, nullptr);

        // a3 = tanh( a2 @ W3^T + b3 )
        gemm_kernel<0, 1><<<dim3(HDIM / 128, MROWS / 128), 256>>>(
            a2, HDIM, W3b, HDIM, b3, a3, HDIM, MROWS, HDIM, HDIM,
            nullptr, 0, nullptr, nullptr);

        softmax_ctx_kernel<<<BATCH, 256>>>(a3, av, enc, ctx);

        // gi = [embed[tgt_t], ctx] @ Wih^T + bih
        gemm_kernel<2, 0><<<dim3(3 * HDIM / 128, 1), 256>>>(
            nullptr, 0, Wihb, 2 * HDIM, bih, gi, 3 * HDIM, BATCH, 3 * HDIM, 2 * HDIM,
            ctx, HDIM, emb, tgt + t);

        gru_kernel<<<BATCH, HDIM>>>(gi, qgh, hi, ho);

        // logits -> d_out (strided rows), then in-place log-softmax
        gemm_kernel<0, 0><<<dim3(VOCAB / 128, 1), 256>>>(
            ho, HDIM, Wob, HDIM, ob, out + (size_t)t * VOCAB, (size_t)NSTEP * VOCAB,
            BATCH, VOCAB, HDIM, nullptr, 0, nullptr, nullptr);

        logsoftmax_kernel<<<BATCH, 1024>>>(out, t);
    }
}

// round 4
// speedup vs baseline: 1.7435x; 1.0292x over previous
#include <cuda_runtime.h>
#include <cuda_bf16.h>
#include <math.h>

#define VOCAB 32000
#define HDIM  512
#define BATCH 128
#define ENCL  64
#define NSTEP 31
#define MROWS (BATCH * ENCL)   // 8192

// ---------------- scratch (static device globals; no allocation) ----------------
__device__ float g_P[MROWS * HDIM];        // enc @ W1a^T  (time-invariant)
__device__ float g_a2[MROWS * HDIM];
__device__ float g_epart[8 * MROWS];       // per-slice partial dots (a3 . v)
__device__ float g_hid[2][BATCH * HDIM];   // ping-pong hidden state
__device__ float g_qgh[BATCH * 2048];      // [q(512) | gh(1536)] per batch row
__device__ float g_ctx[BATCH * HDIM];
__device__ float g_gi[BATCH * 3 * HDIM];
__device__ float g_bqh[2048];              // [b1 | bhh]

// bf16 weight copies (converted once per replay)
__device__ __nv_bfloat16 g_Wp  [HDIM * HDIM];          // W1[:, :H]
__device__ __nv_bfloat16 g_Wqh [2048 * HDIM];          // [W1[:, H:] ; Whh]
__device__ __nv_bfloat16 g_W2  [HDIM * HDIM];
__device__ __nv_bfloat16 g_W3  [HDIM * HDIM];
__device__ __nv_bfloat16 g_Wih [3 * HDIM * 2 * HDIM];
__device__ __nv_bfloat16 g_Wo  [VOCAB * HDIM];

// ---------------- helpers ----------------
__device__ __forceinline__ unsigned bf2(float lo, float hi) {
    unsigned u;
    asm("cvt.rn.bf16x2.f32 %0, %1, %2;" : "=r"(u) : "f"(hi), "f"(lo));
    return u;
}
__device__ __forceinline__ float tanh_fast(float x) {
    float y;
    asm("tanh.approx.f32 %0, %1;" : "=f"(y) : "f"(x));
    return y;
}
__device__ __forceinline__ void mma_bf16(float c[4], const unsigned a[4], const unsigned b[2]) {
    asm volatile(
        "mma.sync.aligned.m16n8k16.row.col.f32.bf16.bf16.f32 "
        "{%0,%1,%2,%3}, {%4,%5,%6,%7}, {%8,%9}, {%0,%1,%2,%3};\n"
        : "+f"(c[0]), "+f"(c[1]), "+f"(c[2]), "+f"(c[3])
        : "r"(a[0]), "r"(a[1]), "r"(a[2]), "r"(a[3]), "r"(b[0]), "r"(b[1]));
}
__device__ __forceinline__ void ldsm4(unsigned& r0, unsigned& r1, unsigned& r2, unsigned& r3,
                                      unsigned addr) {
    asm volatile("ldmatrix.sync.aligned.m8n8.x4.shared.b16 {%0,%1,%2,%3}, [%4];"
                 : "=r"(r0), "=r"(r1), "=r"(r2), "=r"(r3) : "r"(addr));
}

// ---------------- weight conversion (fp32 -> bf16, strided source, float4) ----------------
__global__ void conv_kernel(__nv_bfloat16* __restrict__ dst, const float* __restrict__ src,
                            int rows, int cols, int sld, int soff) {
    const int i4 = (blockIdx.x * blockDim.x + threadIdx.x) * 4;
    if (i4 >= rows * cols) return;
    const int r = i4 / cols, c = i4 - r * cols;   // cols % 4 == 0 everywhere
    float4 v = *(const float4*)(src + (size_t)r * sld + soff + c);
    uint2 o;
    o.x = bf2(v.x, v.y);
    o.y = bf2(v.z, v.w);
    *(uint2*)(dst + i4) = o;
}

__global__ void init_misc_kernel(const float* __restrict__ ench,
                                 const float* __restrict__ b1,
                                 const float* __restrict__ bhh) {
    const int i = blockIdx.x * blockDim.x + threadIdx.x;
    if (i < BATCH * HDIM) g_hid[0][i] = ench[i];
    if (i < 2048) g_bqh[i] = (i < HDIM) ? b1[i] : bhh[i - HDIM];
}

// ---------------- GEMM:  act(A[M,K] * W[N,K]^T + bias),  W bf16, ldmatrix mainloop ----------
// CTA 128x128, warp 32x64 (4x2), K-tile 16. smem tiles row-major, 48B row stride
// (r*48 mod 128 covers all 16B slots -> LDSM conflict-free).
// AMODE 0: A fp32 direct      AMODE 1: tanh(P + Q[row>>6])      AMODE 2: [EMB[TGT] | Q] concat
// ACT 0: bias  ACT 1: bias+tanh  ACT 2: e-dot epilogue: C = e_part[8][M] slices, Q holds v.
// All launches: M,N multiples of tile -> no bounds checks.
template <int AMODE, int ACT>
__global__ __launch_bounds__(256) void gemm_kernel(
    const float* __restrict__ A, int lda,
    const __nv_bfloat16* __restrict__ W, int ldw,
    const float* __restrict__ bias,
    float* __restrict__ C, size_t ldc,
    int M, int N, int K,
    const float* __restrict__ Q, int qld,
    const float* __restrict__ EMB,
    const int* __restrict__ TGT)
{
    __shared__ __align__(16) unsigned char sm[2][2][128 * 48];  // [buf][A/W][row*48+chunk*16]

    const int tid    = threadIdx.x;
    const int warpid = tid >> 5, lane = tid & 31;
    const int wm = warpid >> 1, wn = warpid & 1;
    const int gid = lane >> 2, tidg = lane & 3;
    const int bm0 = blockIdx.y * 128, bn0 = blockIdx.x * 128;
    const int frow = tid >> 1;        // fetch row 0..127
    const int half = tid & 1;         // 16B chunk within k-tile

    const unsigned sbase = (unsigned)__cvta_generic_to_shared(&sm[0][0][0]);
    // per-lane ldmatrix offsets
    unsigned aoff[2], boff[4];
    #pragma unroll
    for (int mi = 0; mi < 2; mi++)
        aoff[mi] = (unsigned)((wm * 32 + mi * 16 + (lane & 15)) * 48 + (lane >> 4) * 16);
    #pragma unroll
    for (int p = 0; p < 4; p++)
        boff[p] = (unsigned)(6144 +
            (wn * 64 + p * 16 + ((lane >> 4) << 3) + (lane & 7)) * 48 + ((lane >> 3) & 1) * 16);

    float acc[2][8][4];
    #pragma unroll
    for (int mi = 0; mi < 2; mi++)
        #pragma unroll
        for (int ni = 0; ni < 8; ni++)
            #pragma unroll
            for (int qq = 0; qq < 4; qq++) acc[mi][ni][qq] = 0.f;

    const int nk = K >> 4;
    float4 pa0, pa1;
    uint4  pw;

    auto fetch = [&](int kt) {
        const int k0 = (kt << 4) + half * 8;
        const int arow = bm0 + frow;
        if (AMODE == 0) {
            pa0 = *(const float4*)(A + (size_t)arow * lda + k0);
            pa1 = *(const float4*)(A + (size_t)arow * lda + k0 + 4);
        } else if (AMODE == 1) {
            float4 p0 = *(const float4*)(A + (size_t)arow * lda + k0);
            float4 p1 = *(const float4*)(A + (size_t)arow * lda + k0 + 4);
            const float* qr = Q + (size_t)(arow >> 6) * qld + k0;
            pa0.x = tanh_fast(p0.x + qr[0]); pa0.y = tanh_fast(p0.y + qr[1]);
            pa0.z = tanh_fast(p0.z + qr[2]); pa0.w = tanh_fast(p0.w + qr[3]);
            pa1.x = tanh_fast(p1.x + qr[4]); pa1.y = tanh_fast(p1.y + qr[5]);
            pa1.z = tanh_fast(p1.z + qr[6]); pa1.w = tanh_fast(p1.w + qr[7]);
        } else {
            if (k0 < HDIM) {
                int tg = TGT[arow * 32];
                tg = max(0, min(tg, VOCAB - 1));
                pa0 = *(const float4*)(EMB + (size_t)tg * HDIM + k0);
                pa1 = *(const float4*)(EMB + (size_t)tg * HDIM + k0 + 4);
            } else {
                pa0 = *(const float4*)(Q + (size_t)arow * qld + (k0 - HDIM));
                pa1 = *(const float4*)(Q + (size_t)arow * qld + (k0 - HDIM) + 4);
            }
        }
        pw = *(const uint4*)(W + (size_t)(bn0 + frow) * ldw + (kt << 4) + half * 8);
    };
    auto store_smem = [&](int buf) {
        uint4 av;
        av.x = bf2(pa0.x, pa0.y); av.y = bf2(pa0.z, pa0.w);
        av.z = bf2(pa1.x, pa1.y); av.w = bf2(pa1.z, pa1.w);
        *(uint4*)&sm[buf][0][frow * 48 + half * 16] = av;
        *(uint4*)&sm[buf][1][frow * 48 + half * 16] = pw;
    };

    fetch(0);
    store_smem(0);
    __syncthreads();

    for (int kt = 0; kt < nk; kt++) {
        const int buf = kt & 1;
        const unsigned sb = sbase + buf * 12288;
        if (kt + 1 < nk) fetch(kt + 1);

        unsigned af[2][4], bfr[8][2];
        #pragma unroll
        for (int mi = 0; mi < 2; mi++)
            ldsm4(af[mi][0], af[mi][1], af[mi][2], af[mi][3], sb + aoff[mi]);
        #pragma unroll
        for (int p = 0; p < 4; p++) {
            unsigned r0, r1, r2, r3;
            ldsm4(r0, r1, r2, r3, sb + boff[p]);
            bfr[2 * p][0] = r0; bfr[2 * p][1] = r1;
            bfr[2 * p + 1][0] = r2; bfr[2 * p + 1][1] = r3;
        }
        #pragma unroll
        for (int mi = 0; mi < 2; mi++)
            #pragma unroll
            for (int ni = 0; ni < 8; ni++)
                mma_bf16(acc[mi][ni], af[mi], bfr[ni]);

        if (kt + 1 < nk) store_smem(buf ^ 1);
        __syncthreads();
    }

    if (ACT == 2) {
        // e-dot epilogue: per-row sum of tanh(acc + b3[col]) * v[col]; Q = v, C = e_part
        const float* v = Q;
        float es[2][2] = {{0.f, 0.f}, {0.f, 0.f}};
        #pragma unroll
        for (int mi = 0; mi < 2; mi++) {
            #pragma unroll
            for (int ni = 0; ni < 8; ni++) {
                const int col = bn0 + wn * 64 + ni * 8 + tidg * 2;
                const float v0 = v[col], v1 = v[col + 1];
                const float b0 = bias[col], b1 = bias[col + 1];
                es[mi][0] += tanh_fast(acc[mi][ni][0] + b0) * v0
                           + tanh_fast(acc[mi][ni][1] + b1) * v1;
                es[mi][1] += tanh_fast(acc[mi][ni][2] + b0) * v0
                           + tanh_fast(acc[mi][ni][3] + b1) * v1;
            }
        }
        const int slice = blockIdx.x * 2 + wn;   // 0..7
        #pragma unroll
        for (int mi = 0; mi < 2; mi++) {
            #pragma unroll
            for (int hh = 0; hh < 2; hh++) {
                float s = es[mi][hh];
                s += __shfl_xor_sync(0xffffffffu, s, 1);
                s += __shfl_xor_sync(0xffffffffu, s, 2);
                if (tidg == 0) {
                    const int row = bm0 + wm * 32 + mi * 16 + gid + hh * 8;
                    C[(size_t)slice * M + row] = s;
                }
            }
        }
        return;
    }

    // standard epilogue: bias (+ optional tanh)
    #pragma unroll
    for (int mi = 0; mi < 2; mi++) {
        #pragma unroll
        for (int ni = 0; ni < 8; ni++) {
            const int col = bn0 + wn * 64 + ni * 8 + tidg * 2;
            const float b0v = bias ? bias[col] : 0.f;
            const float b1v = bias ? bias[col + 1] : 0.f;
            const int row0 = bm0 + wm * 32 + mi * 16 + gid;
            float v0 = acc[mi][ni][0] + b0v, v1 = acc[mi][ni][1] + b1v;
            float v2 = acc[mi][ni][2] + b0v, v3 = acc[mi][ni][3] + b1v;
            if (ACT == 1) {
                v0 = tanh_fast(v0); v1 = tanh_fast(v1);
                v2 = tanh_fast(v2); v3 = tanh_fast(v3);
            }
            C[(size_t)row0 * ldc + col]           = v0;
            C[(size_t)row0 * ldc + col + 1]       = v1;
            C[(size_t)(row0 + 8) * ldc + col]     = v2;
            C[(size_t)(row0 + 8) * ldc + col + 1] = v3;
        }
    }
}

// ---------------- e from partials ; softmax over L ; ctx = alpha^T enc ----------------
__global__ __launch_bounds__(256) void softmax_ctx_kernel(
    const float* __restrict__ epart,
    const float* __restrict__ enc, float* __restrict__ ctx)
{
    __shared__ float e[ENCL];
    __shared__ float alpha[ENCL];
    const int b = blockIdx.x;
    const int tid = threadIdx.x;
    const int warp = tid >> 5, lane = tid & 31;

    if (tid < ENCL) {
        float s = 0.f;
        #pragma unroll
        for (int sl = 0; sl < 8; sl++) s += epart[sl * MROWS + b * ENCL + tid];
        e[tid] = s;
    }
    __syncthreads();
    if (warp == 0) {
        const float e0 = e[lane], e1 = e[lane + 32];
        float m = fmaxf(e0, e1);
        #pragma unroll
        for (int o = 16; o; o >>= 1) m = fmaxf(m, __shfl_xor_sync(0xffffffffu, m, o));
        const float x0 = expf(e0 - m), x1 = expf(e1 - m);
        float s = x0 + x1;
        #pragma unroll
        for (int o = 16; o; o >>= 1) s += __shfl_xor_sync(0xffffffffu, s, o);
        const float inv = 1.f / s;
        alpha[lane]      = x0 * inv;
        alpha[lane + 32] = x1 * inv;
    }
    __syncthreads();
    for (int j = tid; j < HDIM; j += 256) {
        float s = 0.f;
        #pragma unroll
        for (int l = 0; l < ENCL; l++)
            s += alpha[l] * enc[((size_t)b * ENCL + l) * HDIM + j];
        ctx[b * HDIM + j] = s;
    }
}

// ---------------- GRU gate combine (gh lives in qgh[:, 512:]) ----------------
__global__ void gru_kernel(const float* __restrict__ gi, const float* __restrict__ qgh,
                           const float* __restrict__ h, float* __restrict__ hn)
{
    const int b = blockIdx.x, j = threadIdx.x;
    const int o  = b * 3 * HDIM;
    const int og = b * 2048 + HDIM;
    const float r = 1.f / (1.f + expf(-(gi[o + j] + qgh[og + j])));
    const float z = 1.f / (1.f + expf(-(gi[o + HDIM + j] + qgh[og + HDIM + j])));
    const float n = tanhf(gi[o + 2 * HDIM + j] + r * qgh[og + 2 * HDIM + j]);
    const float hv = h[b * HDIM + j];
    hn[b * HDIM + j] = (1.f - z) * n + z * hv;
}

// ---------------- in-place log-softmax over one row of 32000 (single pass, regs) ----------------
__global__ __launch_bounds__(1024) void logsoftmax_kernel(float* __restrict__ out, int t) {
    const int b = blockIdx.x;
    float* row = out + ((size_t)b * NSTEP + t) * VOCAB;
    const int tid = threadIdx.x;
    __shared__ float sm[32];

    float r[32];
    float m = -1e30f;
    #pragma unroll
    for (int i = 0; i < 32; i++) {
        const int idx = tid + (i << 10);
        r[i] = (idx < VOCAB) ? row[idx] : -1e30f;
        m = fmaxf(m, r[i]);
    }
    #pragma unroll
    for (int o = 16; o; o >>= 1) m = fmaxf(m, __shfl_xor_sync(0xffffffffu, m, o));
    if ((tid & 31) == 0) sm[tid >> 5] = m;
    __syncthreads();
    if (tid == 0) {
        float v = sm[0];
        for (int i = 1; i < 32; i++) v = fmaxf(v, sm[i]);
        sm[0] = v;
    }
    __syncthreads();
    m = sm[0];

    float s = 0.f;
    #pragma unroll
    for (int i = 0; i < 32; i++) {
        const int idx = tid + (i << 10);
        if (idx < VOCAB) s += expf(r[i] - m);
    }
    #pragma unroll
    for (int o = 16; o; o >>= 1) s += __shfl_xor_sync(0xffffffffu, s, o);
    __syncthreads();
    if ((tid & 31) == 0) sm[tid >> 5] = s;
    __syncthreads();
    if (tid == 0) {
        float v = 0.f;
        for (int i = 0; i < 32; i++) v += sm[i];
        sm[0] = v;
    }
    __syncthreads();
    const float lse = m + logf(sm[0]);

    #pragma unroll
    for (int i = 0; i < 32; i++) {
        const int idx = tid + (i << 10);
        if (idx < VOCAB) row[idx] = r[i] - lse;
    }
}

// ---------------- launch ----------------
extern "C" void kernel_launch(void* const* d_in, const int* in_sizes, int n_in,
                              void* d_out, int out_size)
{
    const float* enc       = (const float*)d_in[0];
    const float* ench      = (const float*)d_in[1];
    const int* tgt         = (const int*)d_in[2];    // int32 (JAX x64 disabled)
    const float* emb       = (const float*)d_in[3];
    const float* W1        = (const float*)d_in[4];
    const float* b1        = (const float*)d_in[5];
    const float* W2        = (const float*)d_in[6];
    const float* b2        = (const float*)d_in[7];
    const float* W3        = (const float*)d_in[8];
    const float* b3        = (const float*)d_in[9];
    const float* av        = (const float*)d_in[10];
    const float* Wih       = (const float*)d_in[11];
    const float* Whh       = (const float*)d_in[12];
    const float* bih       = (const float*)d_in[13];
    const float* bhh       = (const float*)d_in[14];
    const float* oW        = (const float*)d_in[15];
    const float* ob        = (const float*)d_in[16];
    float* out = (float*)d_out;

    float *P, *a2, *epart, *hidb, *qgh, *ctx, *gi, *bqh;
    __nv_bfloat16 *Wp, *Wqh, *W2b, *W3b, *Wihb, *Wob;
    cudaGetSymbolAddress((void**)&P,     g_P);
    cudaGetSymbolAddress((void**)&a2,    g_a2);
    cudaGetSymbolAddress((void**)&epart, g_epart);
    cudaGetSymbolAddress((void**)&hidb,  g_hid);
    cudaGetSymbolAddress((void**)&qgh,   g_qgh);
    cudaGetSymbolAddress((void**)&ctx,   g_ctx);
    cudaGetSymbolAddress((void**)&gi,    g_gi);
    cudaGetSymbolAddress((void**)&bqh,   g_bqh);
    cudaGetSymbolAddress((void**)&Wp,    g_Wp);
    cudaGetSymbolAddress((void**)&Wqh,   g_Wqh);
    cudaGetSymbolAddress((void**)&W2b,   g_W2);
    cudaGetSymbolAddress((void**)&W3b,   g_W3);
    cudaGetSymbolAddress((void**)&Wihb,  g_Wih);
    cudaGetSymbolAddress((void**)&Wob,   g_Wo);

    init_misc_kernel<<<(BATCH * HDIM + 255) / 256, 256>>>(ench, b1, bhh);

    // weight conversions (fp32 -> bf16, 4 elems/thread)
    conv_kernel<<<(HDIM * HDIM / 4 + 255) / 256, 256>>>(Wp,  W1, HDIM, HDIM, 2 * HDIM, 0);
    conv_kernel<<<(HDIM * HDIM / 4 + 255) / 256, 256>>>(Wqh, W1, HDIM, HDIM, 2 * HDIM, HDIM);
    conv_kernel<<<(3 * HDIM * HDIM / 4 + 255) / 256, 256>>>(Wqh + HDIM * HDIM, Whh, 3 * HDIM, HDIM, HDIM, 0);
    conv_kernel<<<(HDIM * HDIM / 4 + 255) / 256, 256>>>(W2b, W2, HDIM, HDIM, HDIM, 0);
    conv_kernel<<<(HDIM * HDIM / 4 + 255) / 256, 256>>>(W3b, W3, HDIM, HDIM, HDIM, 0);
    conv_kernel<<<(3 * HDIM * 2 * HDIM / 4 + 255) / 256, 256>>>(Wihb, Wih, 3 * HDIM, 2 * HDIM, 2 * HDIM, 0);
    conv_kernel<<<(VOCAB * HDIM / 4 + 255) / 256, 256>>>(Wob, oW, VOCAB, HDIM, HDIM, 0);

    // P = enc @ W1[:, :H]^T   (time-invariant; no bias)
    gemm_kernel<0, 0><<<dim3(HDIM / 128, MROWS / 128), 256>>>(
        enc, HDIM, Wp, HDIM, nullptr, P, HDIM, MROWS, HDIM, HDIM,
        nullptr, 0, nullptr, nullptr);

    for (int t = 0; t < NSTEP; t++) {
        float* hi = hidb + (t & 1) * (BATCH * HDIM);
        float* ho = hidb + ((t + 1) & 1) * (BATCH * HDIM);

        // [q | gh] = hid @ [W1b ; Whh]^T + [b1 | bhh]
        gemm_kernel<0, 0><<<dim3(2048 / 128, 1), 256>>>(
            hi, HDIM, Wqh, HDIM, bqh, qgh, 2048, BATCH, 2048, HDIM,
            nullptr, 0, nullptr, nullptr);

        // a2 = tanh( tanh(P+q) @ W2^T + b2 )
        gemm_kernel<1, 1><<<dim3(HDIM / 128, MROWS / 128), 256>>>(
            P, HDIM, W2b, HDIM, b2, a2, HDIM, MROWS, HDIM, HDIM,
            qgh, 2048, nullptr, nullptr);

        // e_part = slicewise [ tanh(a2 @ W3^T + b3) . v ]    (a3 never materialized)
        gemm_kernel<0, 2><<<dim3(HDIM / 128, MROWS / 128), 256>>>(
            a2, HDIM, W3b, HDIM, b3, epart, 0, MROWS, HDIM, HDIM,
            av, 0, nullptr, nullptr);

        softmax_ctx_kernel<<<BATCH, 256>>>(epart, enc, ctx);

        // gi = [embed[tgt_t], ctx] @ Wih^T + bih
        gemm_kernel<2, 0><<<dim3(3 * HDIM / 128, 1), 256>>>(
            nullptr, 0, Wihb, 2 * HDIM, bih, gi, 3 * HDIM, BATCH, 3 * HDIM, 2 * HDIM,
            ctx, HDIM, emb, tgt + t);

        gru_kernel<<<BATCH, HDIM>>>(gi, qgh, hi, ho);

        // logits -> d_out (strided rows), then in-place log-softmax
        gemm_kernel<0, 0><<<dim3(VOCAB / 128, 1), 256>>>(
            ho, HDIM, Wob, HDIM, ob, out + (size_t)t * VOCAB, (size_t)NSTEP * VOCAB,
            BATCH, VOCAB, HDIM, nullptr, 0, nullptr, nullptr);

        logsoftmax_kernel<<<BATCH, 1024>>>(out, t);
    }
}